// round 11
// baseline (speedup 1.0000x reference)
#include <cuda_runtime.h>
#include <cuda_bf16.h>
#include <cstdint>

#define TPB 128
#define MAXCTAS 592   // 148 SMs * 4 resident CTAs

__device__ __forceinline__ void cp_async16(unsigned int saddr, const void* gptr) {
    asm volatile("cp.async.cg.shared.global [%0], [%1], 16;\n" :: "r"(saddr), "l"(gptr));
}
__device__ __forceinline__ void cp_commit() { asm volatile("cp.async.commit_group;\n"); }
__device__ __forceinline__ void cp_wait1()  { asm volatile("cp.async.wait_group 1;\n" ::: "memory"); }

__global__ void __launch_bounds__(TPB, 4) wvfn_kernel(
    const float* __restrict__ Rs,   // [W,6,3]
    const float* __restrict__ A,    // [6]
    const float* __restrict__ C,    // complex64 viewed as float32
    float* __restrict__ out,        // [W real(out1)][W out2]
    int W, int ntiles)
{
    __shared__ float4 sh4[2][TPB * 18 / 4];   // 2 x 9.2 KB

    const int tid = threadIdx.x;
    const int stride = gridDim.x;

    const float a0  = __ldg(A);
    const float cre = __ldg(C);
    float cim = __ldg(C + 1);
    const float c2v = __ldg(C + 2);
    if (cim == cre && c2v == cre) cim = 0.f;   // real-cast signature
    const float cnorm2 = fmaf(cre, cre, cim * cim);
    const float inv_a0 = __fdividef(1.f, a0);

    // ---- prologue: prefetch first tile into buffer 0 ----
    int tile0 = blockIdx.x;
    if (tile0 < ntiles) {
        int w0 = tile0 * TPB;
        int nw = min(TPB, W - w0);
        int total4 = (nw * 18) >> 2;
        const float4* g4 = (const float4*)(Rs + (size_t)w0 * 18);
        unsigned int sb = (unsigned int)__cvta_generic_to_shared(&sh4[0][0]);
#pragma unroll
        for (int k = 0; k < 5; k++) {
            int i = tid + k * TPB;
            if (i < total4) cp_async16(sb + i * 16, g4 + i);
        }
    }
    cp_commit();

    int buf = 0;
    for (int tile = tile0; tile < ntiles; tile += stride, buf ^= 1) {
        // ---- prefetch next tile ----
        int next = tile + stride;
        if (next < ntiles) {
            int w0n = next * TPB;
            int nwn = min(TPB, W - w0n);
            int total4n = (nwn * 18) >> 2;
            const float4* g4n = (const float4*)(Rs + (size_t)w0n * 18);
            unsigned int sbn = (unsigned int)__cvta_generic_to_shared(&sh4[buf ^ 1][0]);
#pragma unroll
            for (int k = 0; k < 5; k++) {
                int i = tid + k * TPB;
                if (i < total4n) cp_async16(sbn + i * 16, g4n + i);
            }
        }
        cp_commit();
        cp_wait1();
        __syncthreads();

        const int w0 = tile * TPB;
        const int nw = min(TPB, W - w0);
        if (tid < nw) {
            float c[18];
            const float2* my = (const float2*)&sh4[buf][0] + tid * 9;
#pragma unroll
            for (int k = 0; k < 9; k++) {        // conflict-free LDS.64
                float2 v = my[k];
                c[2 * k]     = v.x;
                c[2 * k + 1] = v.y;
            }

            // ---- Phase 1: all diffs + r2, issue all 15 RSQs (pipelined MUFU) ----
            float dxs[15], dys[15], dzs[15], r2s[15], irs[15];
            {
                int p = 0;
#pragma unroll
                for (int a = 0; a < 6; a++) {
#pragma unroll
                    for (int b = a + 1; b < 6; b++) {
                        float dx = c[3*a+0] - c[3*b+0];
                        float dy = c[3*a+1] - c[3*b+1];
                        float dz = c[3*a+2] - c[3*b+2];
                        float r2 = fmaf(dx, dx, fmaf(dy, dy, dz * dz));
                        dxs[p] = dx; dys[p] = dy; dzs[p] = dz; r2s[p] = r2;
                        irs[p] = rsqrtf(r2);     // MUFU.RSQ, back-to-back issue
                        p++;
                    }
                }
            }

            // ---- Phase 2: pure FFMA stream (no MUFU on critical path) ----
            float Gx[6], Gy[6], Gz[6];
#pragma unroll
            for (int a = 0; a < 6; a++) { Gx[a] = 0.f; Gy[a] = 0.f; Gz[a] = 0.f; }
            float S = 0.f, isum = 0.f;
            {
                int p = 0;
#pragma unroll
                for (int a = 0; a < 6; a++) {
#pragma unroll
                    for (int b = a + 1; b < 6; b++) {
                        float ir = irs[p];
                        S    = fmaf(r2s[p], ir, S);   // r = r2 * (1/r)
                        isum += ir;
                        Gx[a] = fmaf(dxs[p],  ir, Gx[a]);
                        Gy[a] = fmaf(dys[p],  ir, Gy[a]);
                        Gz[a] = fmaf(dzs[p],  ir, Gz[a]);
                        Gx[b] = fmaf(dxs[p], -ir, Gx[b]);
                        Gy[b] = fmaf(dys[p], -ir, Gy[b]);
                        Gz[b] = fmaf(dzs[p], -ir, Gz[b]);
                        p++;
                    }
                }
            }

            float g2 = 0.f;
#pragma unroll
            for (int a = 0; a < 6; a++) {
                g2 = fmaf(Gx[a], Gx[a], g2);
                g2 = fmaf(Gy[a], Gy[a], g2);
                g2 = fmaf(Gz[a], Gz[a], g2);
            }

            // VB = 1 exactly: V-term and 1/VB^2 fold away.
            float inv_ord = 2.f * isum;
            float lap     = fmaf(g2 * inv_a0, inv_a0, -2.f * inv_a0 * inv_ord);
            float factor  = fmaf(-0.5f, lap, -0.5f * inv_ord);
            float psi2    = cnorm2 * __expf(-2.f * S * inv_a0);

            const int w = w0 + tid;
            out[w]     = psi2 * factor;
            out[W + w] = psi2;
        }
        __syncthreads();   // reads of sh4[buf] done before refill
    }
}

extern "C" void kernel_launch(void* const* d_in, const int* in_sizes, int n_in,
                              void* d_out, int out_size) {
    const float* Rs = (const float*)d_in[0];
    const float* A  = (const float*)d_in[1];
    const float* C  = (const float*)d_in[2];
    float* out      = (float*)d_out;

    const int W = in_sizes[0] / 18;   // 500000
    const int ntiles = (W + TPB - 1) / TPB;
    const int grid = ntiles < MAXCTAS ? ntiles : MAXCTAS;

    wvfn_kernel<<<grid, TPB>>>(Rs, A, C, out, W, ntiles);
}

// round 12
// speedup vs baseline: 1.1598x; 1.1598x over previous
#include <cuda_runtime.h>
#include <cuda_bf16.h>
#include <cstdint>

#define TPB 128
#define WPT 2                 // walkers per thread
#define TILE_W (TPB * WPT)    // 256 walkers per tile
#define MAXCTAS 888           // 148 SMs * 6 resident CTAs

typedef unsigned long long F2;   // packed f32x2 carrier

__device__ __forceinline__ F2 fma2(F2 a, F2 b, F2 c) {
    F2 d; asm("fma.rn.f32x2 %0, %1, %2, %3;" : "=l"(d) : "l"(a), "l"(b), "l"(c)); return d;
}
__device__ __forceinline__ F2 mul2(F2 a, F2 b) {
    F2 d; asm("mul.rn.f32x2 %0, %1, %2;" : "=l"(d) : "l"(a), "l"(b)); return d;
}
__device__ __forceinline__ F2 add2(F2 a, F2 b) {
    F2 d; asm("add.rn.f32x2 %0, %1, %2;" : "=l"(d) : "l"(a), "l"(b)); return d;
}
__device__ __forceinline__ F2 sub2(F2 a, F2 b) {
    F2 d; asm("sub.rn.f32x2 %0, %1, %2;" : "=l"(d) : "l"(a), "l"(b)); return d;
}
__device__ __forceinline__ F2 pack2(float lo, float hi) {
    F2 d; asm("mov.b64 %0, {%1, %2};" : "=l"(d) : "f"(lo), "f"(hi)); return d;
}
__device__ __forceinline__ void unpack2(F2 v, float& lo, float& hi) {
    asm("mov.b64 {%0, %1}, %2;" : "=f"(lo), "=f"(hi) : "l"(v));
}

__device__ __forceinline__ void cp_async16(unsigned int saddr, const void* gptr) {
    asm volatile("cp.async.cg.shared.global [%0], [%1], 16;\n" :: "r"(saddr), "l"(gptr));
}
__device__ __forceinline__ void cp_commit() { asm volatile("cp.async.commit_group;\n"); }
__device__ __forceinline__ void cp_wait1()  { asm volatile("cp.async.wait_group 1;\n" ::: "memory"); }

__global__ void __launch_bounds__(TPB, 6) wvfn_kernel(
    const float* __restrict__ Rs,   // [W,6,3]
    const float* __restrict__ A,    // [6]
    const float* __restrict__ C,    // complex64 viewed as float32
    float* __restrict__ out,        // [W real(out1)][W out2]
    int W, int ntiles)
{
    __shared__ float4 sh4[2][TILE_W * 18 / 4];   // 2 x 18.4 KB

    const int tid = threadIdx.x;
    const int stride = gridDim.x;

    const float a0  = __ldg(A);
    const float cre = __ldg(C);
    float cim = __ldg(C + 1);
    const float c2v = __ldg(C + 2);
    if (cim == cre && c2v == cre) cim = 0.f;   // real-cast signature
    const float cnorm2 = fmaf(cre, cre, cim * cim);
    const float inv_a0 = __fdividef(1.f, a0);

    const F2 NEG1 = 0xBF800000BF800000ULL;     // (-1.f, -1.f)

    // ---- prologue: prefetch first tile ----
    int tile0 = blockIdx.x;
    if (tile0 < ntiles) {
        int w0 = tile0 * TILE_W;
        int nw = min(TILE_W, W - w0);
        int total4 = (nw * 18) >> 2;
        const float4* g4 = (const float4*)(Rs + (size_t)w0 * 18);
        unsigned int sb = (unsigned int)__cvta_generic_to_shared(&sh4[0][0]);
#pragma unroll
        for (int k = 0; k < 9; k++) {
            int i = tid + k * TPB;
            if (i < total4) cp_async16(sb + i * 16, g4 + i);
        }
    }
    cp_commit();

    int buf = 0;
    for (int tile = tile0; tile < ntiles; tile += stride, buf ^= 1) {
        int next = tile + stride;
        if (next < ntiles) {
            int w0n = next * TILE_W;
            int nwn = min(TILE_W, W - w0n);
            int total4n = (nwn * 18) >> 2;
            const float4* g4n = (const float4*)(Rs + (size_t)w0n * 18);
            unsigned int sbn = (unsigned int)__cvta_generic_to_shared(&sh4[buf ^ 1][0]);
#pragma unroll
            for (int k = 0; k < 9; k++) {
                int i = tid + k * TPB;
                if (i < total4n) cp_async16(sbn + i * 16, g4n + i);
            }
        }
        cp_commit();
        cp_wait1();
        __syncthreads();

        const int w0 = tile * TILE_W;
        const int nw = min(TILE_W, W - w0);

        // walker A = w0 + tid, walker B = w0 + TPB + tid (stride keeps LDS conflict-free)
        const float2* sb2 = (const float2*)&sh4[buf][0];
        float ca[18], cb[18];
        {
            const float2* pa = sb2 + tid * 9;
            const float2* pb = sb2 + (tid + TPB) * 9;
#pragma unroll
            for (int k = 0; k < 9; k++) {               // conflict-free LDS.64
                float2 va = pa[k];  ca[2*k] = va.x; ca[2*k+1] = va.y;
                float2 vb = pb[k];  cb[2*k] = vb.x; cb[2*k+1] = vb.y;
            }
        }

        F2 cx[6], cy[6], cz[6];
#pragma unroll
        for (int a = 0; a < 6; a++) {
            cx[a] = pack2(ca[3*a+0], cb[3*a+0]);
            cy[a] = pack2(ca[3*a+1], cb[3*a+1]);
            cz[a] = pack2(ca[3*a+2], cb[3*a+2]);
        }

        F2 Gx[6], Gy[6], Gz[6];
#pragma unroll
        for (int a = 0; a < 6; a++) { Gx[a] = 0ULL; Gy[a] = 0ULL; Gz[a] = 0ULL; }
        F2 S = 0ULL, isum = 0ULL;

#pragma unroll
        for (int a = 0; a < 6; a++) {
#pragma unroll
            for (int b = a + 1; b < 6; b++) {
                F2 dx = sub2(cx[a], cx[b]);
                F2 dy = sub2(cy[a], cy[b]);
                F2 dz = sub2(cz[a], cz[b]);
                F2 r2 = fma2(dx, dx, fma2(dy, dy, mul2(dz, dz)));
                float r2l, r2h; unpack2(r2, r2l, r2h);
                F2 ir  = pack2(rsqrtf(r2l), rsqrtf(r2h));   // 2x MUFU.RSQ
                F2 irn = mul2(ir, NEG1);                     // exact negation
                S    = fma2(r2, ir, S);                      // r = r2 * (1/r)
                isum = add2(isum, ir);
                Gx[a] = fma2(dx, ir,  Gx[a]);
                Gy[a] = fma2(dy, ir,  Gy[a]);
                Gz[a] = fma2(dz, ir,  Gz[a]);
                Gx[b] = fma2(dx, irn, Gx[b]);
                Gy[b] = fma2(dy, irn, Gy[b]);
                Gz[b] = fma2(dz, irn, Gz[b]);
            }
        }

        F2 g2p = 0ULL;
#pragma unroll
        for (int a = 0; a < 6; a++) {
            g2p = fma2(Gx[a], Gx[a], g2p);
            g2p = fma2(Gy[a], Gy[a], g2p);
            g2p = fma2(Gz[a], Gz[a], g2p);
        }

        float Sl, Sh, il, ih, g2l, g2h;
        unpack2(S, Sl, Sh);
        unpack2(isum, il, ih);
        unpack2(g2p, g2l, g2h);

        // VB = 1 exactly: V-term and 1/VB^2 fold away.
        if (tid < nw) {                                  // walker A
            float inv_ord = 2.f * il;
            float lap    = fmaf(g2l * inv_a0, inv_a0, -2.f * inv_a0 * inv_ord);
            float factor = fmaf(-0.5f, lap, -0.5f * inv_ord);
            float psi2   = cnorm2 * __expf(-2.f * Sl * inv_a0);
            int w = w0 + tid;
            out[w]     = psi2 * factor;
            out[W + w] = psi2;
        }
        if (TPB + tid < nw) {                            // walker B
            float inv_ord = 2.f * ih;
            float lap    = fmaf(g2h * inv_a0, inv_a0, -2.f * inv_a0 * inv_ord);
            float factor = fmaf(-0.5f, lap, -0.5f * inv_ord);
            float psi2   = cnorm2 * __expf(-2.f * Sh * inv_a0);
            int w = w0 + TPB + tid;
            out[w]     = psi2 * factor;
            out[W + w] = psi2;
        }
        __syncthreads();   // all reads of sh4[buf] done before refill
    }
}

extern "C" void kernel_launch(void* const* d_in, const int* in_sizes, int n_in,
                              void* d_out, int out_size) {
    const float* Rs = (const float*)d_in[0];
    const float* A  = (const float*)d_in[1];
    const float* C  = (const float*)d_in[2];
    float* out      = (float*)d_out;

    const int W = in_sizes[0] / 18;   // 500000
    const int ntiles = (W + TILE_W - 1) / TILE_W;
    const int grid = ntiles < MAXCTAS ? ntiles : MAXCTAS;

    wvfn_kernel<<<grid, TPB>>>(Rs, A, C, out, W, ntiles);
}

// round 13
// speedup vs baseline: 1.3459x; 1.1604x over previous
#include <cuda_runtime.h>
#include <cuda_bf16.h>
#include <cstdint>

#define TPB 256
#define NWARPS (TPB / 32)
#define MAXCTAS 888            // 148 SMs * 6 resident CTAs
#define TILE4 144              // 32 walkers * 18 floats / 4 = float4 count per warp-tile

__device__ __forceinline__ void cp_async16(unsigned int saddr, const void* gptr) {
    asm volatile("cp.async.cg.shared.global [%0], [%1], 16;\n" :: "r"(saddr), "l"(gptr));
}
__device__ __forceinline__ void cp_commit() { asm volatile("cp.async.commit_group;\n"); }
__device__ __forceinline__ void cp_wait1()  { asm volatile("cp.async.wait_group 1;\n" ::: "memory"); }

__global__ void __launch_bounds__(TPB, 6) wvfn_kernel(
    const float* __restrict__ Rs,   // [W,6,3]
    const float* __restrict__ A,    // [6]
    const float* __restrict__ C,    // complex64 viewed as float32
    float* __restrict__ out,        // [W real(out1)][W out2]
    int W, int ntiles)              // ntiles = warp-tiles of 32 walkers
{
    // per-warp private double buffers: no block-level synchronization anywhere
    __shared__ float4 sh[NWARPS][2][TILE4];   // 8 * 2 * 2304 B = 36.9 KB

    const int tid  = threadIdx.x;
    const int wid  = tid >> 5;
    const int lane = tid & 31;

    const int gw0     = blockIdx.x * NWARPS + wid;   // this warp's first tile
    const int wstride = gridDim.x * NWARPS;

    const float a0  = __ldg(A);
    const float cre = __ldg(C);
    float cim = __ldg(C + 1);
    const float c2v = __ldg(C + 2);
    if (cim == cre && c2v == cre) cim = 0.f;   // real-cast signature
    const float cnorm2 = fmaf(cre, cre, cim * cim);
    const float inv_a0 = __fdividef(1.f, a0);

    // ---- prologue: prefetch this warp's first tile into buf 0 ----
    if (gw0 < ntiles) {
        const float4* g4 = (const float4*)(Rs + (size_t)gw0 * 32 * 18);
        unsigned int sb = (unsigned int)__cvta_generic_to_shared(&sh[wid][0][0]);
#pragma unroll
        for (int k = 0; k < 5; k++) {          // 144 float4 over 32 lanes
            int i = lane + k * 32;
            if (i < TILE4) cp_async16(sb + i * 16, g4 + i);
        }
    }
    cp_commit();

    int buf = 0;
    for (int tile = gw0; tile < ntiles; tile += wstride, buf ^= 1) {
        // ---- prefetch next tile into the other buffer ----
        int next = tile + wstride;
        if (next < ntiles) {
            const float4* g4n = (const float4*)(Rs + (size_t)next * 32 * 18);
            unsigned int sbn = (unsigned int)__cvta_generic_to_shared(&sh[wid][buf ^ 1][0]);
#pragma unroll
            for (int k = 0; k < 5; k++) {
                int i = lane + k * 32;
                if (i < TILE4) cp_async16(sbn + i * 16, g4n + i);
            }
        }
        cp_commit();
        cp_wait1();          // current tile's data landed (prev group drained)
        __syncwarp();

        // ---- compute: walker = tile*32 + lane ----
        const int w = tile * 32 + lane;
        if (w < W) {
            float c[18];
            const float2* my = (const float2*)&sh[wid][buf][0] + lane * 9;
#pragma unroll
            for (int k = 0; k < 9; k++) {      // conflict-free LDS.64 (stride 18 words)
                float2 v = my[k];
                c[2 * k]     = v.x;
                c[2 * k + 1] = v.y;
            }

            float Gx[6], Gy[6], Gz[6];
#pragma unroll
            for (int a = 0; a < 6; a++) { Gx[a] = 0.f; Gy[a] = 0.f; Gz[a] = 0.f; }
            float S = 0.f, isum = 0.f;

#pragma unroll
            for (int a = 0; a < 6; a++) {
#pragma unroll
                for (int b = a + 1; b < 6; b++) {
                    float dx = c[3*a+0] - c[3*b+0];
                    float dy = c[3*a+1] - c[3*b+1];
                    float dz = c[3*a+2] - c[3*b+2];
                    float r2 = fmaf(dx, dx, fmaf(dy, dy, dz * dz));
                    float ir = rsqrtf(r2);      // MUFU.RSQ
                    S    = fmaf(r2, ir, S);     // r = r2 * (1/r)
                    isum += ir;
                    Gx[a] = fmaf(dx,  ir, Gx[a]);
                    Gy[a] = fmaf(dy,  ir, Gy[a]);
                    Gz[a] = fmaf(dz,  ir, Gz[a]);
                    Gx[b] = fmaf(dx, -ir, Gx[b]);
                    Gy[b] = fmaf(dy, -ir, Gy[b]);
                    Gz[b] = fmaf(dz, -ir, Gz[b]);
                }
            }

            float g2 = 0.f;
#pragma unroll
            for (int a = 0; a < 6; a++) {
                g2 = fmaf(Gx[a], Gx[a], g2);
                g2 = fmaf(Gy[a], Gy[a], g2);
                g2 = fmaf(Gz[a], Gz[a], g2);
            }

            // VB = 1 exactly: V-term and 1/VB^2 fold away.
            float inv_ord = 2.f * isum;
            float lap     = fmaf(g2 * inv_a0, inv_a0, -2.f * inv_a0 * inv_ord);
            float factor  = fmaf(-0.5f, lap, -0.5f * inv_ord);
            float psi2    = cnorm2 * __expf(-2.f * S * inv_a0);

            out[w]     = psi2 * factor;
            out[W + w] = psi2;
        }
        __syncwarp();        // all lanes done reading sh[wid][buf] before it refills
    }
}

extern "C" void kernel_launch(void* const* d_in, const int* in_sizes, int n_in,
                              void* d_out, int out_size) {
    const float* Rs = (const float*)d_in[0];
    const float* A  = (const float*)d_in[1];
    const float* C  = (const float*)d_in[2];
    float* out      = (float*)d_out;

    const int W = in_sizes[0] / 18;            // 500000
    const int ntiles = (W + 31) / 32;          // 15625 warp-tiles (exact, no tail)
    int ctas = (ntiles + NWARPS - 1) / NWARPS;
    if (ctas > MAXCTAS) ctas = MAXCTAS;

    wvfn_kernel<<<ctas, TPB>>>(Rs, A, C, out, W, ntiles);
}

// round 14
// speedup vs baseline: 1.5888x; 1.1805x over previous
#include <cuda_runtime.h>
#include <cuda_bf16.h>
#include <cstdint>

#define TPB 256

__global__ void __launch_bounds__(TPB) wvfn_kernel(
    const float* __restrict__ Rs,   // [W,6,3]
    const float* __restrict__ A,    // [6]
    const float* __restrict__ C,    // complex64 viewed as float32
    float* __restrict__ out,        // [W real(out1)][W out2]
    int W)
{
    const int w = blockIdx.x * TPB + threadIdx.x;
    if (w >= W) return;

    // Direct load of this walker's 18 floats: 9 x LDG.64 (8B-aligned for every w).
    // Full line utilization within each warp; 9-deep MLP issued back-to-back.
    const float2* p = (const float2*)(Rs + (size_t)w * 18);
    float c[18];
#pragma unroll
    for (int k = 0; k < 9; k++) {
        float2 v = __ldg(p + k);
        c[2 * k]     = v.x;
        c[2 * k + 1] = v.y;
    }

    float Gx[6], Gy[6], Gz[6];
#pragma unroll
    for (int a = 0; a < 6; a++) { Gx[a] = 0.f; Gy[a] = 0.f; Gz[a] = 0.f; }

    float S = 0.f;      // sum_{i<j} r_ij
    float isum = 0.f;   // sum_{i<j} 1/r_ij

#pragma unroll
    for (int a = 0; a < 6; a++) {
#pragma unroll
        for (int b = a + 1; b < 6; b++) {
            float dx = c[3*a+0] - c[3*b+0];
            float dy = c[3*a+1] - c[3*b+1];
            float dz = c[3*a+2] - c[3*b+2];
            float r2 = fmaf(dx, dx, fmaf(dy, dy, dz * dz));
            float ir = rsqrtf(r2);          // MUFU.RSQ
            S    = fmaf(r2, ir, S);         // r = r2 * (1/r)
            isum += ir;
            Gx[a] = fmaf(dx,  ir, Gx[a]);
            Gy[a] = fmaf(dy,  ir, Gy[a]);
            Gz[a] = fmaf(dz,  ir, Gz[a]);
            Gx[b] = fmaf(dx, -ir, Gx[b]);
            Gy[b] = fmaf(dy, -ir, Gy[b]);
            Gz[b] = fmaf(dz, -ir, Gz[b]);
        }
    }

    float g2 = 0.f;
#pragma unroll
    for (int a = 0; a < 6; a++) {
        g2 = fmaf(Gx[a], Gx[a], g2);
        g2 = fmaf(Gy[a], Gy[a], g2);
        g2 = fmaf(Gz[a], Gz[a], g2);
    }

    const float a0 = __ldg(A);

    // C arrives either real-cast ([re0,re1,re2,...]) or interleaved ([re0,im0,...]).
    const float cre = __ldg(C);
    float cim = __ldg(C + 1);
    const float c2v = __ldg(C + 2);
    if (cim == cre && c2v == cre) cim = 0.f;   // real-cast signature
    const float cnorm2 = fmaf(cre, cre, cim * cim);

    // VB = alpha*CF = 1.0 exactly -> V-term and 1/VB^2 fold away.
    float inv_ord = 2.f * isum;                         // ordered-pair sum of 1/r
    float inv_a0  = __fdividef(1.f, a0);                // MUFU.RCP
    float lap     = fmaf(g2 * inv_a0, inv_a0, -2.f * inv_a0 * inv_ord);
    float factor  = fmaf(-0.5f, lap, -0.5f * inv_ord);  // K + V (real)
    float e2      = __expf(-2.f * S * inv_a0);          // exp(-2S/a0)
    float psi2    = cnorm2 * e2;                        // |psi|^2

    out[w]     = psi2 * factor;   // Output 0: real(out1)
    out[W + w] = psi2;            // Output 1: |psi|^2
}

extern "C" void kernel_launch(void* const* d_in, const int* in_sizes, int n_in,
                              void* d_out, int out_size) {
    const float* Rs = (const float*)d_in[0];
    const float* A  = (const float*)d_in[1];
    const float* C  = (const float*)d_in[2];
    float* out      = (float*)d_out;

    const int W = in_sizes[0] / 18;   // 500000
    const int grid = (W + TPB - 1) / TPB;
    wvfn_kernel<<<grid, TPB>>>(Rs, A, C, out, W);
}